// round 5
// baseline (speedup 1.0000x reference)
#include <cuda_runtime.h>
#include <cstdint>

#define BATCH    8192
#define HID      128
#define GATES    512
#define LOOKBACK 48
#define HORIZON  12
#define TSTEPS   60
#define DIN      8
#define STATE    (BATCH*HID)
#define KROW0    160          // 8 x-cols + 24 zero pad + 128 h-cols
#define KROW1    256
#define NCTA     128

// ---- device globals (no allocation allowed) ----
__device__ float g_WB0[KROW0*GATES];   // k-major [k][n], n = unit*4+gate
__device__ float g_WB1[KROW1*GATES];
__device__ float g_b0 [GATES];
__device__ float g_b1 [GATES];
__device__ float g_h0 [2*STATE];
__device__ float g_h1 [2*STATE];
__device__ float g_c0 [STATE];
__device__ float g_c1 [STATE];
__device__ float g_fcp[2*BATCH];       // fc partial sums per n-slice

__device__ unsigned g_barcnt = 0;
__device__ volatile unsigned g_bargen = 0;

// ---- smem layout ----
// header floats: bias0 [0,256), bias1 [256,512), wfc [512,640), pred [640,768)
#define HDR_B0   0
#define HDR_B1   256
#define HDR_WFC  512
#define HDR_PRED 640
#define SM_AS(b)  (3072 + (b)*18432)            // A: 128x36 f32
#define SM_BS(b)  (3072 + 36864 + (b)*33792)    // B: 32x264 f32
#define SM_CB     3072                          // epilogue aliases A/B (dead)
#define SM_HB     (3072 + 33280)
#define SMEM_TOTAL 107520

// ---------------- helpers ----------------
__device__ __forceinline__ float rna_tf32(float x){
    uint32_t u; asm("cvt.rna.tf32.f32 %0, %1;" : "=r"(u) : "f"(x));
    return __uint_as_float(u);
}
__device__ __forceinline__ uint32_t smem_u32(const void* p){
    uint32_t a;
    asm("{ .reg .u64 t; cvta.to.shared.u64 t, %1; cvt.u32.u64 %0, t; }" : "=r"(a) : "l"(p));
    return a;
}
__device__ __forceinline__ void cpa16(uint32_t dst, const void* src){
    asm volatile("cp.async.cg.shared.global [%0], [%1], 16;" :: "r"(dst), "l"(src));
}
__device__ __forceinline__ void mma8(float* d, const uint32_t* a, const uint32_t* b){
    asm volatile("mma.sync.aligned.m16n8k8.row.col.f32.tf32.tf32.f32 "
        "{%0,%1,%2,%3}, {%4,%5,%6,%7}, {%8,%9}, {%0,%1,%2,%3};"
        : "+f"(d[0]), "+f"(d[1]), "+f"(d[2]), "+f"(d[3])
        : "r"(a[0]), "r"(a[1]), "r"(a[2]), "r"(a[3]), "r"(b[0]), "r"(b[1]));
}
__device__ __forceinline__ float sigm_f(float x){
    x = fminf(fmaxf(x, -30.f), 30.f);
    return __fdividef(1.f, 1.f + __expf(-x));
}
__device__ __forceinline__ float tanh_f(float x){
    x = fminf(fmaxf(x, -15.f), 15.f);
    float e = __expf(2.f*x);
    return 1.f - __fdividef(2.f, e + 1.f);
}
__device__ __forceinline__ void grid_barrier(){
    __syncthreads();
    if (threadIdx.x == 0){
        __threadfence();
        unsigned gen = g_bargen;
        if (atomicAdd(&g_barcnt, 1u) == NCTA - 1u){
            g_barcnt = 0;
            __threadfence();
            g_bargen = gen + 1u;
        } else {
            while (g_bargen == gen) __nanosleep(32);
        }
        __threadfence();
    }
    __syncthreads();
}

// ---------------- weight repack (k-major, tf32-rounded) + state zero ----------------
__global__ void prep_kernel(const float* __restrict__ Wih0, const float* __restrict__ Whh0,
                            const float* __restrict__ bih0, const float* __restrict__ bhh0,
                            const float* __restrict__ Wih1, const float* __restrict__ Whh1,
                            const float* __restrict__ bih1, const float* __restrict__ bhh1)
{
    const int NW0 = KROW0*GATES, NW1 = KROW1*GATES;
    const int total = NW0 + NW1 + 2*GATES + 4*STATE;
    for (int idx = blockIdx.x*blockDim.x + threadIdx.x; idx < total;
         idx += gridDim.x*blockDim.x) {
        int i = idx;
        if (i < NW0) { int k = i>>9, n = i&511; int row = (n&3)*HID + (n>>2);
            float v = 0.f;
            if (k < DIN)       v = Wih0[row*DIN + k];
            else if (k >= 32)  v = Whh0[row*HID + (k-32)];
            g_WB0[i] = rna_tf32(v); continue; }
        i -= NW0;
        if (i < NW1) { int k = i>>9, n = i&511; int row = (n&3)*HID + (n>>2);
            float v = (k < HID) ? Wih1[row*HID + k] : Whh1[row*HID + (k-HID)];
            g_WB1[i] = rna_tf32(v); continue; }
        i -= NW1;
        if (i < GATES) { int row = (i&3)*HID + (i>>2); g_b0[i] = bih0[row]+bhh0[row]; continue; }
        i -= GATES;
        if (i < GATES) { int row = (i&3)*HID + (i>>2); g_b1[i] = bih1[row]+bhh1[row]; continue; }
        i -= GATES;
        if (i < STATE) { g_h0[i] = 0.f; continue; }
        i -= STATE;
        if (i < STATE) { g_h1[i] = 0.f; continue; }
        i -= STATE;
        if (i < STATE) { g_c0[i] = 0.f; continue; }
        i -= STATE;
        g_c1[i] = 0.f;
    }
}

// ---------------- one fused LSTM cell phase (M=128 x N=256 tile per CTA) ----------------
template<int NCH, bool ISL0>
__device__ __forceinline__ void cell_phase(
    const float* __restrict__ xsrc, int sx,
    const float* __restrict__ hprev,
    const float* __restrict__ WB,
    const float* __restrict__ bsm,
    float* __restrict__ cglob, float* __restrict__ hout,
    const float* __restrict__ predb, bool use_bg,
    char* smem, uint32_t sbase,
    int tid, int lane, int wid, int m0, int n0,
    const float* __restrict__ wfcs, int slice)
{
    const int wm0 = (wid >> 2) * 64, wn0 = (wid & 3) * 64;
    const int r = lane >> 2, cq = lane & 3;

    float acc[4][8][4];
    #pragma unroll
    for (int a = 0; a < 4; a++)
        #pragma unroll
        for (int b = 0; b < 8; b++)
            #pragma unroll
            for (int d = 0; d < 4; d++) acc[a][b][d] = 0.f;

    auto issue = [&](int j){
        const int b = j & 1;
        const uint32_t asb = sbase + SM_AS(b);
        const uint32_t bsb = sbase + SM_BS(b);
        const float* wsrc = WB + (size_t)(j*32)*GATES + n0;
        #pragma unroll
        for (int i = 0; i < 8; i++) {          // B: 32 k-rows x 256 n
            int idx = tid + i*256;
            int kk = idx >> 6, q = idx & 63;
            cpa16(bsb + (uint32_t)(kk*264 + q*4)*4, wsrc + (size_t)kk*GATES + q*4);
        }
        if (!(ISL0 && j == 0)) {               // A: 128 m x 32 k
            const float* ap; int koff, ss;
            if (ISL0)           { ap = hprev; ss = HID; koff = (j-1)*32; }
            else if (j < 4)     { ap = xsrc;  ss = sx;  koff = j*32; }
            else                { ap = hprev; ss = HID; koff = (j-4)*32; }
            #pragma unroll
            for (int i = 0; i < 4; i++) {
                int idx = tid + i*256;
                int m = idx >> 3, q = idx & 7;
                cpa16(asb + (uint32_t)(m*36 + q*4)*4, ap + (size_t)(m0+m)*ss + koff + q*4);
            }
        }
    };

    if (ISL0) {                                // chunk0: x cols (cvt + BG) + zero pad
        float* As0 = (float*)(smem + SM_AS(0));
        int m = tid >> 1, hh = tid & 1;
        #pragma unroll
        for (int cc = 0; cc < 16; cc++) {
            int k = hh*16 + cc;
            float v = 0.f;
            if (k < DIN) {
                v = (use_bg && k == 0) ? predb[m] : xsrc[(size_t)(m0+m)*sx + k];
                v = rna_tf32(v);
            }
            As0[m*36 + k] = v;
        }
    }
    issue(0);
    asm volatile("cp.async.commit_group;" ::: "memory");

    for (int j = 0; j < NCH; j++) {
        const int b = j & 1;
        if (j + 1 < NCH) {
            issue(j + 1);
            asm volatile("cp.async.commit_group;" ::: "memory");
            asm volatile("cp.async.wait_group 1;" ::: "memory");
        } else {
            asm volatile("cp.async.wait_group 0;" ::: "memory");
        }
        __syncthreads();
        const uint32_t* As = (const uint32_t*)(smem + SM_AS(b));
        const uint32_t* Bs = (const uint32_t*)(smem + SM_BS(b));
        #pragma unroll
        for (int s = 0; s < 4; s++) {
            uint32_t af[4][4];
            #pragma unroll
            for (int mi = 0; mi < 4; mi++) {
                int row0 = wm0 + mi*16 + r;
                af[mi][0] = As[ row0   *36 + s*8 + cq];
                af[mi][1] = As[(row0+8)*36 + s*8 + cq];
                af[mi][2] = As[ row0   *36 + s*8 + cq + 4];
                af[mi][3] = As[(row0+8)*36 + s*8 + cq + 4];
            }
            uint32_t bf[8][2];
            #pragma unroll
            for (int nj = 0; nj < 8; nj++) {
                int colb = wn0 + nj*8 + r;
                bf[nj][0] = Bs[(s*8     + cq)*264 + colb];
                bf[nj][1] = Bs[(s*8 + 4 + cq)*264 + colb];
            }
            #pragma unroll
            for (int mi = 0; mi < 4; mi++)
                #pragma unroll
                for (int nj = 0; nj < 8; nj++)
                    mma8(acc[mi][nj], af[mi], bf[nj]);
        }
        __syncthreads();
    }

    // -------- epilogue --------
    float* cbuf = (float*)(smem + SM_CB);
    float* hbuf = (float*)(smem + SM_HB);
    const int ub = n0 >> 2;
    #pragma unroll
    for (int i = 0; i < 8; i++) {
        int idx = tid + i*256;
        int m = idx >> 4, q = idx & 15;
        float4 v = *(const float4*)&cglob[(size_t)(m0+m)*HID + ub + q*4];
        cbuf[m*65 + q*4 + 0] = v.x; cbuf[m*65 + q*4 + 1] = v.y;
        cbuf[m*65 + q*4 + 2] = v.z; cbuf[m*65 + q*4 + 3] = v.w;
    }
    __syncthreads();
    #pragma unroll
    for (int mi = 0; mi < 4; mi++) {
        #pragma unroll
        for (int nj = 0; nj < 8; nj++) {
            int nl = wn0 + nj*8 + 2*cq;
            float v0 = acc[mi][nj][0] + bsm[nl];
            float v1 = acc[mi][nj][1] + bsm[nl+1];
            float v2 = acc[mi][nj][2] + bsm[nl];
            float v3 = acc[mi][nj][3] + bsm[nl+1];
            float p0 = __shfl_xor_sync(0xffffffffu, v0, 1);
            float p1 = __shfl_xor_sync(0xffffffffu, v1, 1);
            float p2 = __shfl_xor_sync(0xffffffffu, v2, 1);
            float p3 = __shfl_xor_sync(0xffffffffu, v3, 1);
            if (!(lane & 1)) {
                int u  = (wn0 + nj*8 + 2*cq) >> 2;
                int ml = wm0 + mi*16 + r;
                {
                    float cold = cbuf[ml*65 + u];
                    float cn = sigm_f(v1)*cold + sigm_f(v0)*tanh_f(p0);
                    cbuf[ml*65 + u] = cn;
                    hbuf[ml*65 + u] = rna_tf32(sigm_f(p1)*tanh_f(cn));
                }
                {
                    float cold = cbuf[(ml+8)*65 + u];
                    float cn = sigm_f(v3)*cold + sigm_f(v2)*tanh_f(p2);
                    cbuf[(ml+8)*65 + u] = cn;
                    hbuf[(ml+8)*65 + u] = rna_tf32(sigm_f(p3)*tanh_f(cn));
                }
            }
        }
    }
    __syncthreads();
    #pragma unroll
    for (int i = 0; i < 8; i++) {
        int idx = tid + i*256;
        int m = idx >> 4, q = idx & 15;
        float4 cv, hv;
        cv.x = cbuf[m*65 + q*4 + 0]; cv.y = cbuf[m*65 + q*4 + 1];
        cv.z = cbuf[m*65 + q*4 + 2]; cv.w = cbuf[m*65 + q*4 + 3];
        hv.x = hbuf[m*65 + q*4 + 0]; hv.y = hbuf[m*65 + q*4 + 1];
        hv.z = hbuf[m*65 + q*4 + 2]; hv.w = hbuf[m*65 + q*4 + 3];
        *(float4*)&cglob[(size_t)(m0+m)*HID + ub + q*4] = cv;
        *(float4*)&hout [(size_t)(m0+m)*HID + ub + q*4] = hv;
    }
    if (!ISL0) {                               // fc partial: this CTA's 64 units
        int row = tid >> 1, half = tid & 1;
        float s = 0.f;
        #pragma unroll
        for (int j = 0; j < 32; j++) {
            int u = half*32 + j;
            s += hbuf[row*65 + u] * wfcs[ub + u];
        }
        s += __shfl_xor_sync(0xffffffffu, s, 1);
        if (!half) g_fcp[slice*BATCH + m0 + row] = s;
    }
}

// ---------------- persistent driver: all 60 timesteps, both layers, fc ----------------
__global__ __launch_bounds__(256, 1) void lstm_persistent(
    const float* __restrict__ inputs,
    const float* __restrict__ Wfc,
    const float* __restrict__ bfc,
    float* __restrict__ out)
{
    extern __shared__ __align__(16) char smem[];
    const int tid = threadIdx.x, lane = tid & 31, wid = tid >> 5;
    const int bx = blockIdx.x;
    const int m0 = (bx >> 1) * 128;
    const int n0 = (bx & 1) * 256;
    const int slice = bx & 1;
    const uint32_t sbase = smem_u32(smem);
    float* hdr = (float*)smem;

    hdr[HDR_B0 + tid] = g_b0[n0 + tid];
    hdr[HDR_B1 + tid] = g_b1[n0 + tid];
    if (tid < HID) hdr[HDR_WFC + tid] = Wfc[tid];
    const float bfcv = bfc[0];
    __syncthreads();

    for (int t = 0; t < TSTEPS; t++) {
        const int rp = t & 1, wp = 1 - rp;
        const bool use_bg = (t > LOOKBACK);
        if (use_bg) {
            if (tid < 128) {
                float pv = bfcv + __ldcg(&g_fcp[m0 + tid]) + __ldcg(&g_fcp[BATCH + m0 + tid]);
                hdr[HDR_PRED + tid] = pv;
                if (n0 == 0) out[(size_t)(m0 + tid)*HORIZON + (t - 1 - LOOKBACK)] = pv;
            }
            __syncthreads();
        }
        cell_phase<KROW0/32, true>(
            inputs + t*DIN, TSTEPS*DIN,
            g_h0 + rp*STATE, g_WB0,
            hdr + HDR_B0,
            g_c0, g_h0 + wp*STATE,
            hdr + HDR_PRED, use_bg,
            smem, sbase, tid, lane, wid, m0, n0,
            hdr + HDR_WFC, slice);
        grid_barrier();
        cell_phase<KROW1/32, false>(
            g_h0 + wp*STATE, HID,
            g_h1 + rp*STATE, g_WB1,
            hdr + HDR_B1,
            g_c1, g_h1 + wp*STATE,
            hdr + HDR_PRED, false,
            smem, sbase, tid, lane, wid, m0, n0,
            hdr + HDR_WFC, slice);
        grid_barrier();
    }
    if (n0 == 0 && tid < 128) {
        float pv = bfcv + __ldcg(&g_fcp[m0 + tid]) + __ldcg(&g_fcp[BATCH + m0 + tid]);
        out[(size_t)(m0 + tid)*HORIZON + (HORIZON - 1)] = pv;
    }
}

// ---------------- launch ----------------
extern "C" void kernel_launch(void* const* d_in, const int* in_sizes, int n_in,
                              void* d_out, int out_size)
{
    const float* inputs = (const float*)d_in[0];
    const float* Wih0 = (const float*)d_in[1];
    const float* Whh0 = (const float*)d_in[2];
    const float* bih0 = (const float*)d_in[3];
    const float* bhh0 = (const float*)d_in[4];
    const float* Wih1 = (const float*)d_in[5];
    const float* Whh1 = (const float*)d_in[6];
    const float* bih1 = (const float*)d_in[7];
    const float* bhh1 = (const float*)d_in[8];
    const float* Wfc  = (const float*)d_in[9];
    const float* bfc  = (const float*)d_in[10];
    float* out = (float*)d_out;

    cudaFuncSetAttribute(lstm_persistent, cudaFuncAttributeMaxDynamicSharedMemorySize, SMEM_TOTAL);

    prep_kernel<<<2048, 256>>>(Wih0, Whh0, bih0, bhh0, Wih1, Whh1, bih1, bhh1);
    lstm_persistent<<<NCTA, 256, SMEM_TOTAL>>>(inputs, Wfc, bfc, out);
}

// round 6
// speedup vs baseline: 1.3314x; 1.3314x over previous
#include <cuda_runtime.h>
#include <cstdint>

#define BATCH    8192
#define HID      128
#define GATES    512
#define LOOKBACK 48
#define HORIZON  12
#define TSTEPS   60
#define DIN      8
#define STATE    (BATCH*HID)
#define KROW0    160          // 8 x-cols + 24 zero pad + 128 h-cols
#define KROW1    256
#define NTHR     512

// ---- device globals (no allocation allowed) ----
__device__ float g_WB0[KROW0*GATES];   // k-major [k][n], n = unit*4+gate
__device__ float g_WB1[KROW1*GATES];
__device__ float g_b0 [GATES];
__device__ float g_b1 [GATES];
__device__ float g_h0 [2*STATE];
__device__ float g_h1 [2*STATE];
__device__ float g_c0 [STATE];
__device__ float g_c1 [STATE];
__device__ float g_pred[BATCH];

// ---- smem layout (bytes) ----
// bias: [0,1024). A bufs: 128x36 f32. B bufs: 32x264 f32.
// epilogue cbuf/hbuf (128x65 f32 each) alias A/B staging (dead by then).
#define SM_AS(b)  (1024 + (b)*18432)
#define SM_BS(b)  (1024 + 36864 + (b)*33792)
#define SM_CB     1024
#define SM_HB     (1024 + 33280)
#define SMEM_TOTAL 105472

// ---------------- helpers ----------------
__device__ __forceinline__ float rna_tf32(float x){
    uint32_t u; asm("cvt.rna.tf32.f32 %0, %1;" : "=r"(u) : "f"(x));
    return __uint_as_float(u);
}
__device__ __forceinline__ uint32_t smem_u32(const void* p){
    uint32_t a;
    asm("{ .reg .u64 t; cvta.to.shared.u64 t, %1; cvt.u32.u64 %0, t; }" : "=r"(a) : "l"(p));
    return a;
}
__device__ __forceinline__ void cpa16(uint32_t dst, const void* src){
    asm volatile("cp.async.cg.shared.global [%0], [%1], 16;" :: "r"(dst), "l"(src));
}
__device__ __forceinline__ void mma8(float* d, const uint32_t* a, const uint32_t* b){
    asm volatile("mma.sync.aligned.m16n8k8.row.col.f32.tf32.tf32.f32 "
        "{%0,%1,%2,%3}, {%4,%5,%6,%7}, {%8,%9}, {%0,%1,%2,%3};"
        : "+f"(d[0]), "+f"(d[1]), "+f"(d[2]), "+f"(d[3])
        : "r"(a[0]), "r"(a[1]), "r"(a[2]), "r"(a[3]), "r"(b[0]), "r"(b[1]));
}
__device__ __forceinline__ float sigm_f(float x){
    x = fminf(fmaxf(x, -30.f), 30.f);
    return __fdividef(1.f, 1.f + __expf(-x));
}
__device__ __forceinline__ float tanh_f(float x){
    x = fminf(fmaxf(x, -15.f), 15.f);
    float e = __expf(2.f*x);
    return 1.f - __fdividef(2.f, e + 1.f);
}

// ---------------- weight repack (k-major, tf32-rounded) + state zero ----------------
__global__ void prep_kernel(const float* __restrict__ Wih0, const float* __restrict__ Whh0,
                            const float* __restrict__ bih0, const float* __restrict__ bhh0,
                            const float* __restrict__ Wih1, const float* __restrict__ Whh1,
                            const float* __restrict__ bih1, const float* __restrict__ bhh1)
{
    const int NW0 = KROW0*GATES, NW1 = KROW1*GATES;
    const int total = NW0 + NW1 + 2*GATES + 4*STATE;
    for (int idx = blockIdx.x*blockDim.x + threadIdx.x; idx < total;
         idx += gridDim.x*blockDim.x) {
        int i = idx;
        if (i < NW0) { int k = i>>9, n = i&511; int row = (n&3)*HID + (n>>2);
            float v = 0.f;
            if (k < DIN)       v = Wih0[row*DIN + k];
            else if (k >= 32)  v = Whh0[row*HID + (k-32)];
            g_WB0[i] = rna_tf32(v); continue; }
        i -= NW0;
        if (i < NW1) { int k = i>>9, n = i&511; int row = (n&3)*HID + (n>>2);
            float v = (k < HID) ? Wih1[row*HID + k] : Whh1[row*HID + (k-HID)];
            g_WB1[i] = rna_tf32(v); continue; }
        i -= NW1;
        if (i < GATES) { int row = (i&3)*HID + (i>>2); g_b0[i] = bih0[row]+bhh0[row]; continue; }
        i -= GATES;
        if (i < GATES) { int row = (i&3)*HID + (i>>2); g_b1[i] = bih1[row]+bhh1[row]; continue; }
        i -= GATES;
        if (i < STATE) { g_h0[i] = 0.f; continue; }
        i -= STATE;
        if (i < STATE) { g_h1[i] = 0.f; continue; }
        i -= STATE;
        if (i < STATE) { g_c0[i] = 0.f; continue; }
        i -= STATE;
        g_c1[i] = 0.f;
    }
}

// ---------------- fused LSTM cell: tf32 mma.sync, 512 thr, M=128 x N=256 tile ----------------
// 16 warps in 2(m) x 8(n) grid; warp tile 64 x 32.
__global__ __launch_bounds__(NTHR, 1) void lstm_cell_mma(
    const float* __restrict__ xsrc, int sx, int Kx,
    const float* __restrict__ bg,
    const float* __restrict__ hprev,
    const float* __restrict__ WB, int Krow,
    const float* __restrict__ bias,
    float* __restrict__ cglob, float* __restrict__ hout)
{
    extern __shared__ __align__(16) char smem[];
    const int tid = threadIdx.x, lane = tid & 31, wid = tid >> 5;
    const int m0 = blockIdx.x * 128, n0 = blockIdx.y * 256;
    const int wm0 = (wid >> 3) * 64, wn0 = (wid & 7) * 32;
    const int r = lane >> 2, cq = lane & 3;
    const uint32_t sbase = smem_u32(smem);

    if (tid < 256) ((float*)smem)[tid] = bias[n0 + tid];

    float acc[4][4][4];
    #pragma unroll
    for (int a = 0; a < 4; a++)
        #pragma unroll
        for (int b = 0; b < 4; b++)
            #pragma unroll
            for (int d = 0; d < 4; d++) acc[a][b][d] = 0.f;

    const int nch = Krow >> 5;

    // -------- chunk issue (cp.async) --------
    auto issue = [&](int j){
        const int b = j & 1;
        const uint32_t asb = sbase + SM_AS(b);
        const uint32_t bsb = sbase + SM_BS(b);
        const float* wsrc = WB + (size_t)(j*32)*GATES + n0;
        #pragma unroll
        for (int i = 0; i < 4; i++) {          // B: 32 k-rows x 256 n
            int idx = tid + i*NTHR;
            int kk = idx >> 6, q = idx & 63;
            cpa16(bsb + (uint32_t)(kk*264 + q*4)*4, wsrc + (size_t)kk*GATES + q*4);
        }
        if (!(Kx == DIN && j == 0)) {          // A: 128 m x 32 k
            const float* ap; int koff, ss;
            if (Kx == DIN)      { ap = hprev; ss = HID; koff = (j-1)*32; }
            else if (j < 4)     { ap = xsrc;  ss = sx;  koff = j*32; }
            else                { ap = hprev; ss = HID; koff = (j-4)*32; }
            #pragma unroll
            for (int i = 0; i < 2; i++) {
                int idx = tid + i*NTHR;
                int m = idx >> 3, q = idx & 7;
                cpa16(asb + (uint32_t)(m*36 + q*4)*4, ap + (size_t)(m0+m)*ss + koff + q*4);
            }
        }
    };

    // layer-0 chunk 0: x cols (tf32-cvt + BG feedback) + zero pad, manual STS
    if (Kx == DIN) {
        float* As0 = (float*)(smem + SM_AS(0));
        int m = tid >> 2, hh = tid & 3;
        #pragma unroll
        for (int cc = 0; cc < 8; cc++) {
            int k = hh*8 + cc;
            float v = 0.f;
            if (k < DIN) {
                v = (bg && k == 0) ? bg[m0+m] : xsrc[(size_t)(m0+m)*sx + k];
                v = rna_tf32(v);
            }
            As0[m*36 + k] = v;
        }
    }
    issue(0);
    asm volatile("cp.async.commit_group;" ::: "memory");

    // -------- mainloop --------
    for (int j = 0; j < nch; j++) {
        const int b = j & 1;
        if (j + 1 < nch) {
            issue(j + 1);
            asm volatile("cp.async.commit_group;" ::: "memory");
            asm volatile("cp.async.wait_group 1;" ::: "memory");
        } else {
            asm volatile("cp.async.wait_group 0;" ::: "memory");
        }
        __syncthreads();
        const uint32_t* As = (const uint32_t*)(smem + SM_AS(b));
        const uint32_t* Bs = (const uint32_t*)(smem + SM_BS(b));
        #pragma unroll
        for (int s = 0; s < 4; s++) {
            uint32_t af[4][4];
            #pragma unroll
            for (int mi = 0; mi < 4; mi++) {
                int row0 = wm0 + mi*16 + r;
                af[mi][0] = As[ row0   *36 + s*8 + cq];
                af[mi][1] = As[(row0+8)*36 + s*8 + cq];
                af[mi][2] = As[ row0   *36 + s*8 + cq + 4];
                af[mi][3] = As[(row0+8)*36 + s*8 + cq + 4];
            }
            uint32_t bf[4][2];
            #pragma unroll
            for (int nj = 0; nj < 4; nj++) {
                int colb = wn0 + nj*8 + r;
                bf[nj][0] = Bs[(s*8     + cq)*264 + colb];
                bf[nj][1] = Bs[(s*8 + 4 + cq)*264 + colb];
            }
            #pragma unroll
            for (int mi = 0; mi < 4; mi++)
                #pragma unroll
                for (int nj = 0; nj < 4; nj++)
                    mma8(acc[mi][nj], af[mi], bf[nj]);
        }
        __syncthreads();
    }

    // -------- epilogue --------
    float* cbuf = (float*)(smem + SM_CB);
    float* hbuf = (float*)(smem + SM_HB);
    const int ub = n0 >> 2;            // unit base (global) for this CTA
    #pragma unroll
    for (int i = 0; i < 4; i++) {      // cold: global -> smem, coalesced
        int idx = tid + i*NTHR;
        int m = idx >> 4, q = idx & 15;
        float4 v = *(const float4*)&cglob[(size_t)(m0+m)*HID + ub + q*4];
        cbuf[m*65 + q*4 + 0] = v.x; cbuf[m*65 + q*4 + 1] = v.y;
        cbuf[m*65 + q*4 + 2] = v.z; cbuf[m*65 + q*4 + 3] = v.w;
    }
    __syncthreads();
    const float* bsm = (const float*)smem;
    #pragma unroll
    for (int mi = 0; mi < 4; mi++) {
        #pragma unroll
        for (int nj = 0; nj < 4; nj++) {
            int nl = wn0 + nj*8 + 2*cq;
            float v0 = acc[mi][nj][0] + bsm[nl];
            float v1 = acc[mi][nj][1] + bsm[nl+1];
            float v2 = acc[mi][nj][2] + bsm[nl];
            float v3 = acc[mi][nj][3] + bsm[nl+1];
            float p0 = __shfl_xor_sync(0xffffffffu, v0, 1);
            float p1 = __shfl_xor_sync(0xffffffffu, v1, 1);
            float p2 = __shfl_xor_sync(0xffffffffu, v2, 1);
            float p3 = __shfl_xor_sync(0xffffffffu, v3, 1);
            if (!(lane & 1)) {         // even lanes hold (i,f); partner held (g,o)
                int u  = (wn0 + nj*8 + 2*cq) >> 2;
                int ml = wm0 + mi*16 + r;
                {
                    float cold = cbuf[ml*65 + u];
                    float cn = sigm_f(v1)*cold + sigm_f(v0)*tanh_f(p0);
                    cbuf[ml*65 + u] = cn;
                    hbuf[ml*65 + u] = rna_tf32(sigm_f(p1)*tanh_f(cn));
                }
                {
                    float cold = cbuf[(ml+8)*65 + u];
                    float cn = sigm_f(v3)*cold + sigm_f(v2)*tanh_f(p2);
                    cbuf[(ml+8)*65 + u] = cn;
                    hbuf[(ml+8)*65 + u] = rna_tf32(sigm_f(p3)*tanh_f(cn));
                }
            }
        }
    }
    __syncthreads();
    #pragma unroll
    for (int i = 0; i < 4; i++) {      // writeback, coalesced
        int idx = tid + i*NTHR;
        int m = idx >> 4, q = idx & 15;
        float4 cv, hv;
        cv.x = cbuf[m*65 + q*4 + 0]; cv.y = cbuf[m*65 + q*4 + 1];
        cv.z = cbuf[m*65 + q*4 + 2]; cv.w = cbuf[m*65 + q*4 + 3];
        hv.x = hbuf[m*65 + q*4 + 0]; hv.y = hbuf[m*65 + q*4 + 1];
        hv.z = hbuf[m*65 + q*4 + 2]; hv.w = hbuf[m*65 + q*4 + 3];
        *(float4*)&cglob[(size_t)(m0+m)*HID + ub + q*4] = cv;
        *(float4*)&hout [(size_t)(m0+m)*HID + ub + q*4] = hv;
    }
}

// ---------------- fc head ----------------
__global__ void fc_kernel(const float* __restrict__ h1, const float* __restrict__ Wfc,
                          const float* __restrict__ bfc, float* __restrict__ out,
                          float* __restrict__ pred, int tstep)
{
    int gtid = blockIdx.x*blockDim.x + threadIdx.x;
    int row  = gtid >> 5;
    int lane = gtid & 31;
    if (row >= BATCH) return;
    const float* hr = h1 + (size_t)row*HID;
    float s = 0.f;
    #pragma unroll
    for (int k = lane; k < HID; k += 32) s += hr[k]*Wfc[k];
    #pragma unroll
    for (int o = 16; o > 0; o >>= 1) s += __shfl_xor_sync(0xffffffffu, s, o);
    if (lane == 0) {
        float p = s + bfc[0];
        out[row*HORIZON + tstep] = p;
        pred[row] = p;
    }
}

// ---------------- launch ----------------
extern "C" void kernel_launch(void* const* d_in, const int* in_sizes, int n_in,
                              void* d_out, int out_size)
{
    const float* inputs = (const float*)d_in[0];
    const float* Wih0 = (const float*)d_in[1];
    const float* Whh0 = (const float*)d_in[2];
    const float* bih0 = (const float*)d_in[3];
    const float* bhh0 = (const float*)d_in[4];
    const float* Wih1 = (const float*)d_in[5];
    const float* Whh1 = (const float*)d_in[6];
    const float* bih1 = (const float*)d_in[7];
    const float* bhh1 = (const float*)d_in[8];
    const float* Wfc  = (const float*)d_in[9];
    const float* bfc  = (const float*)d_in[10];
    float* out = (float*)d_out;

    float *pWB0,*pWB1,*pb0,*pb1,*ph0,*ph1,*pc0,*pc1,*ppred;
    cudaGetSymbolAddress((void**)&pWB0, g_WB0);
    cudaGetSymbolAddress((void**)&pWB1, g_WB1);
    cudaGetSymbolAddress((void**)&pb0 , g_b0 );
    cudaGetSymbolAddress((void**)&pb1 , g_b1 );
    cudaGetSymbolAddress((void**)&ph0 , g_h0 );
    cudaGetSymbolAddress((void**)&ph1 , g_h1 );
    cudaGetSymbolAddress((void**)&pc0 , g_c0 );
    cudaGetSymbolAddress((void**)&pc1 , g_c1 );
    cudaGetSymbolAddress((void**)&ppred, g_pred);

    cudaFuncSetAttribute(lstm_cell_mma, cudaFuncAttributeMaxDynamicSharedMemorySize, SMEM_TOTAL);

    prep_kernel<<<2048, 256>>>(Wih0, Whh0, bih0, bhh0, Wih1, Whh1, bih1, bhh1);

    dim3 grid(BATCH/128, GATES/256);
    for (int t = 0; t < TSTEPS; t++) {
        int rp = t & 1;
        int wp = 1 - rp;
        int use_bg = (t > LOOKBACK) ? 1 : 0;
        lstm_cell_mma<<<grid, NTHR, SMEM_TOTAL>>>(
            inputs + t*DIN, TSTEPS*DIN, DIN,
            use_bg ? ppred : (const float*)nullptr,
            ph0 + rp*STATE, pWB0, KROW0, pb0,
            pc0, ph0 + wp*STATE);
        lstm_cell_mma<<<grid, NTHR, SMEM_TOTAL>>>(
            ph0 + wp*STATE, HID, HID,
            (const float*)nullptr,
            ph1 + rp*STATE, pWB1, KROW1, pb1,
            pc1, ph1 + wp*STATE);
        if (t >= LOOKBACK)
            fc_kernel<<<BATCH/8, 256>>>(ph1 + wp*STATE, Wfc, bfc, out, ppred,
                                        t - LOOKBACK);
    }
}

// round 7
// speedup vs baseline: 1.6969x; 1.2745x over previous
#include <cuda_runtime.h>
#include <cuda_fp16.h>
#include <cstdint>

#define BATCH    8192
#define HID      128
#define GATES    512
#define LOOKBACK 48
#define HORIZON  12
#define TSTEPS   60
#define DIN      8
#define STATE    (BATCH*HID)
#define KROW0    160          // 8 x-cols + 24 zero pad + 128 h-cols (halves)
#define KROW1    256
#define NTHR     512

// ---- device globals (no allocation allowed) ----
__device__ __half g_WB0[GATES*KROW0];   // n-major [n][k], n = unit*4+gate
__device__ __half g_WB1[GATES*KROW1];
__device__ float  g_b0 [GATES];
__device__ float  g_b1 [GATES];
__device__ __half g_h0 [2*STATE];
__device__ __half g_h1 [2*STATE];
__device__ float  g_c0 [STATE];
__device__ float  g_c1 [STATE];
__device__ float  g_fcp[2*BATCH];       // fc partials per n-slice

// ---- smem layout (bytes) ----
// bias 256f @0, wfc 128f @1024, pred 128f @1536
// A bufs: 128 x 40 halves (10240B): A0@2048 A1@12288
// B bufs: 256 x 40 halves (20480B): B0@22528 B1@43008  (end 63488)
// epilogue aliases staging: cbuf f32 128x65 @2048 (33280B), hbuf half 128x66 @35328 (16896B)
#define SM_A(b)   (2048 + (b)*10240)
#define SM_B(b)   (22528 + (b)*20480)
#define SM_CB     2048
#define SM_HB     35328
#define SMEM_TOTAL 63488

// ---------------- helpers ----------------
__device__ __forceinline__ uint32_t smem_u32(const void* p){
    uint32_t a;
    asm("{ .reg .u64 t; cvta.to.shared.u64 t, %1; cvt.u32.u64 %0, t; }" : "=r"(a) : "l"(p));
    return a;
}
__device__ __forceinline__ void cpa16(uint32_t dst, const void* src){
    asm volatile("cp.async.cg.shared.global [%0], [%1], 16;" :: "r"(dst), "l"(src));
}
__device__ __forceinline__ void mma16(float* d, const uint32_t* a, const uint32_t* b){
    asm volatile("mma.sync.aligned.m16n8k16.row.col.f32.f16.f16.f32 "
        "{%0,%1,%2,%3}, {%4,%5,%6,%7}, {%8,%9}, {%0,%1,%2,%3};"
        : "+f"(d[0]), "+f"(d[1]), "+f"(d[2]), "+f"(d[3])
        : "r"(a[0]), "r"(a[1]), "r"(a[2]), "r"(a[3]), "r"(b[0]), "r"(b[1]));
}
__device__ __forceinline__ float sigm_f(float x){
    x = fminf(fmaxf(x, -30.f), 30.f);
    return __fdividef(1.f, 1.f + __expf(-x));
}
__device__ __forceinline__ float tanh_f(float x){
    x = fminf(fmaxf(x, -15.f), 15.f);
    float e = __expf(2.f*x);
    return 1.f - __fdividef(2.f, e + 1.f);
}

// ---------------- weight repack (n-major fp16) + state zero ----------------
__global__ void prep_kernel(const float* __restrict__ Wih0, const float* __restrict__ Whh0,
                            const float* __restrict__ bih0, const float* __restrict__ bhh0,
                            const float* __restrict__ Wih1, const float* __restrict__ Whh1,
                            const float* __restrict__ bih1, const float* __restrict__ bhh1)
{
    const int NW0 = GATES*KROW0, NW1 = GATES*KROW1;
    const int total = NW0 + NW1 + 2*GATES + 4*STATE;
    for (int idx = blockIdx.x*blockDim.x + threadIdx.x; idx < total;
         idx += gridDim.x*blockDim.x) {
        int i = idx;
        if (i < NW0) { int n = i/KROW0, k = i%KROW0; int row = (n&3)*HID + (n>>2);
            float v = 0.f;
            if (k < DIN)       v = Wih0[row*DIN + k];
            else if (k >= 32)  v = Whh0[row*HID + (k-32)];
            g_WB0[i] = __float2half_rn(v); continue; }
        i -= NW0;
        if (i < NW1) { int n = i>>8, k = i&255; int row = (n&3)*HID + (n>>2);
            float v = (k < HID) ? Wih1[row*HID + k] : Whh1[row*HID + (k-HID)];
            g_WB1[i] = __float2half_rn(v); continue; }
        i -= NW1;
        if (i < GATES) { int row = (i&3)*HID + (i>>2); g_b0[i] = bih0[row]+bhh0[row]; continue; }
        i -= GATES;
        if (i < GATES) { int row = (i&3)*HID + (i>>2); g_b1[i] = bih1[row]+bhh1[row]; continue; }
        i -= GATES;
        if (i < STATE) { g_h0[i] = __ushort_as_half((unsigned short)0); continue; }
        i -= STATE;
        if (i < STATE) { g_h1[i] = __ushort_as_half((unsigned short)0); continue; }
        i -= STATE;
        if (i < STATE) { g_c0[i] = 0.f; continue; }
        i -= STATE;
        g_c1[i] = 0.f;
    }
}

// ---------------- fused LSTM cell: fp16 mma.sync, 512 thr, M=128 x N=256 tile ----------------
// 16 warps in 2(m) x 8(n); warp tile 64 x 32; K chunks of 32 halves, double buffered.
__global__ __launch_bounds__(NTHR, 1) void lstm_cell(
    const float* __restrict__ xf, int sx,
    const __half* __restrict__ asrc0, const __half* __restrict__ asrc1,
    const __half* __restrict__ WB, int Krow,
    const float* __restrict__ bias,
    float* __restrict__ cglob, __half* __restrict__ hout,
    const float* __restrict__ Wfc, const float* __restrict__ bfc,
    float* __restrict__ fcp, float* __restrict__ out,
    int isl0, int use_bg, int outcol, int dofc)
{
    extern __shared__ __align__(16) char smem[];
    const int tid = threadIdx.x, lane = tid & 31, wid = tid >> 5;
    const int m0 = blockIdx.x * 128, n0 = blockIdx.y * 256, slice = blockIdx.y;
    const int wm0 = (wid >> 3) * 64, wn0 = (wid & 7) * 32;
    const int g = lane >> 2, tq = lane & 3;
    const uint32_t sbase = smem_u32(smem);
    float* bsm  = (float*)smem;
    float* wfcs = (float*)(smem + 1024);
    float* predS= (float*)(smem + 1536);

    if (tid < 256) bsm[tid] = bias[n0 + tid];
    if (tid < 128) wfcs[tid] = Wfc[tid];

    if (use_bg) {                      // combine fc partials from previous step
        if (tid < 128) {
            float pv = bfc[0] + fcp[m0 + tid] + fcp[BATCH + m0 + tid];
            predS[tid] = pv;
            if (n0 == 0) out[(size_t)(m0 + tid)*HORIZON + outcol] = pv;
        }
        __syncthreads();
    }

    float acc[4][4][4];
    #pragma unroll
    for (int a = 0; a < 4; a++)
        #pragma unroll
        for (int b = 0; b < 4; b++)
            #pragma unroll
            for (int d = 0; d < 4; d++) acc[a][b][d] = 0.f;

    const int nch = Krow >> 5;

    auto issue = [&](int j){
        const int b = j & 1;
        const uint32_t asb = sbase + SM_A(b);
        const uint32_t bsb = sbase + SM_B(b);
        const char* wsrc = (const char*)WB + ((size_t)n0*Krow + j*32)*2;
        #pragma unroll
        for (int i = 0; i < 2; i++) {              // B: 256 n-rows x 32 k halves (64B/row)
            int idx = tid + i*NTHR;
            int row = idx >> 2, q = idx & 3;
            cpa16(bsb + (uint32_t)(row*80 + q*16), wsrc + (size_t)row*Krow*2 + q*16);
        }
        if (!(isl0 && j == 0)) {                   // A: 128 m-rows x 32 k halves
            const __half* ap; int koff;
            if (isl0)       { ap = asrc0; koff = (j-1)*32; }
            else if (j < 4) { ap = asrc0; koff = j*32; }
            else            { ap = asrc1; koff = (j-4)*32; }
            int row = tid >> 2, q = tid & 3;
            cpa16(asb + (uint32_t)(row*80 + q*16),
                  (const char*)(ap + (size_t)(m0+row)*HID + koff) + q*16);
        }
    };

    if (isl0) {                                    // chunk0: x cols (f32->f16 + BG) + zero pad
        __half* As0 = (__half*)(smem + SM_A(0));
        int m = tid >> 2, part = tid & 3;
        __half hv[8];
        #pragma unroll
        for (int c = 0; c < 8; c++) {
            int k = part*8 + c;
            float v = 0.f;
            if (k < DIN) v = (use_bg && k == 0) ? predS[m] : xf[(size_t)(m0+m)*sx + k];
            hv[c] = __float2half_rn(v);
        }
        *(uint4*)&As0[m*40 + part*8] = *(uint4*)hv;
    }
    issue(0);
    asm volatile("cp.async.commit_group;" ::: "memory");

    for (int j = 0; j < nch; j++) {
        const int b = j & 1;
        if (j + 1 < nch) {
            issue(j + 1);
            asm volatile("cp.async.commit_group;" ::: "memory");
            asm volatile("cp.async.wait_group 1;" ::: "memory");
        } else {
            asm volatile("cp.async.wait_group 0;" ::: "memory");
        }
        __syncthreads();
        const uint32_t* As = (const uint32_t*)(smem + SM_A(b));  // word stride 20
        const uint32_t* Bs = (const uint32_t*)(smem + SM_B(b));  // word stride 20
        #pragma unroll
        for (int s = 0; s < 2; s++) {
            uint32_t af[4][4];
            #pragma unroll
            for (int mi = 0; mi < 4; mi++) {
                int row0 = wm0 + mi*16 + g;
                af[mi][0] = As[ row0   *20 + s*8 + tq];
                af[mi][1] = As[(row0+8)*20 + s*8 + tq];
                af[mi][2] = As[ row0   *20 + s*8 + tq + 4];
                af[mi][3] = As[(row0+8)*20 + s*8 + tq + 4];
            }
            uint32_t bf[4][2];
            #pragma unroll
            for (int nj = 0; nj < 4; nj++) {
                int nn = wn0 + nj*8 + g;
                bf[nj][0] = Bs[nn*20 + s*8 + tq];
                bf[nj][1] = Bs[nn*20 + s*8 + tq + 4];
            }
            #pragma unroll
            for (int mi = 0; mi < 4; mi++)
                #pragma unroll
                for (int nj = 0; nj < 4; nj++)
                    mma16(acc[mi][nj], af[mi], bf[nj]);
        }
        __syncthreads();
    }

    // -------- epilogue --------
    float*  cbuf = (float*)(smem + SM_CB);    // 128 x 65 f32
    __half* hbuf = (__half*)(smem + SM_HB);   // 128 x 66 half
    const int ub = n0 >> 2;
    #pragma unroll
    for (int i = 0; i < 4; i++) {             // c old: global -> smem, coalesced
        int idx = tid + i*NTHR;
        int m = idx >> 4, q = idx & 15;
        float4 v = *(const float4*)&cglob[(size_t)(m0+m)*HID + ub + q*4];
        cbuf[m*65 + q*4 + 0] = v.x; cbuf[m*65 + q*4 + 1] = v.y;
        cbuf[m*65 + q*4 + 2] = v.z; cbuf[m*65 + q*4 + 3] = v.w;
    }
    __syncthreads();
    #pragma unroll
    for (int mi = 0; mi < 4; mi++) {
        #pragma unroll
        for (int nj = 0; nj < 4; nj++) {
            int nl = wn0 + nj*8 + 2*tq;
            float v0 = acc[mi][nj][0] + bsm[nl];
            float v1 = acc[mi][nj][1] + bsm[nl+1];
            float v2 = acc[mi][nj][2] + bsm[nl];
            float v3 = acc[mi][nj][3] + bsm[nl+1];
            float p0 = __shfl_xor_sync(0xffffffffu, v0, 1);
            float p1 = __shfl_xor_sync(0xffffffffu, v1, 1);
            float p2 = __shfl_xor_sync(0xffffffffu, v2, 1);
            float p3 = __shfl_xor_sync(0xffffffffu, v3, 1);
            if (!(lane & 1)) {                 // even lanes: (i,f); partner: (g,o)
                int u  = nl >> 2;
                int ml = wm0 + mi*16 + g;
                {
                    float cold = cbuf[ml*65 + u];
                    float cn = sigm_f(v1)*cold + sigm_f(v0)*tanh_f(p0);
                    cbuf[ml*65 + u] = cn;
                    hbuf[ml*66 + u] = __float2half_rn(sigm_f(p1)*tanh_f(cn));
                }
                {
                    float cold = cbuf[(ml+8)*65 + u];
                    float cn = sigm_f(v3)*cold + sigm_f(v2)*tanh_f(p2);
                    cbuf[(ml+8)*65 + u] = cn;
                    hbuf[(ml+8)*66 + u] = __float2half_rn(sigm_f(p3)*tanh_f(cn));
                }
            }
        }
    }
    __syncthreads();
    if (dofc && tid < 256) {                   // fc partial over this CTA's 64 units
        int row = tid >> 1, hf = tid & 1;
        float s = 0.f;
        #pragma unroll
        for (int jj = 0; jj < 32; jj++) {
            int u = hf*32 + jj;
            s += __half2float(hbuf[row*66 + u]) * wfcs[ub + u];
        }
        s += __shfl_xor_sync(0xffffffffu, s, 1);
        if (!hf) fcp[slice*BATCH + m0 + row] = s;
    }
    #pragma unroll
    for (int i = 0; i < 4; i++) {             // c writeback, coalesced
        int idx = tid + i*NTHR;
        int m = idx >> 4, q = idx & 15;
        float4 cv;
        cv.x = cbuf[m*65 + q*4 + 0]; cv.y = cbuf[m*65 + q*4 + 1];
        cv.z = cbuf[m*65 + q*4 + 2]; cv.w = cbuf[m*65 + q*4 + 3];
        *(float4*)&cglob[(size_t)(m0+m)*HID + ub + q*4] = cv;
    }
    const uint32_t* hw = (const uint32_t*)hbuf;
    #pragma unroll
    for (int i = 0; i < 2; i++) {             // h writeback (half), coalesced
        int idx = tid + i*NTHR;
        int m = idx >> 3, q = idx & 7;
        uint4 w;
        int bw = m*33 + q*4;
        w.x = hw[bw]; w.y = hw[bw+1]; w.z = hw[bw+2]; w.w = hw[bw+3];
        *(uint4*)&hout[(size_t)(m0+m)*HID + ub + q*8] = w;
    }
}

// ---------------- tail: last horizon column ----------------
__global__ void fc_tail(const float* __restrict__ fcp, const float* __restrict__ bfc,
                        float* __restrict__ out)
{
    int row = blockIdx.x*128 + threadIdx.x;
    out[(size_t)row*HORIZON + (HORIZON-1)] = bfc[0] + fcp[row] + fcp[BATCH + row];
}

// ---------------- launch ----------------
extern "C" void kernel_launch(void* const* d_in, const int* in_sizes, int n_in,
                              void* d_out, int out_size)
{
    const float* inputs = (const float*)d_in[0];
    const float* Wih0 = (const float*)d_in[1];
    const float* Whh0 = (const float*)d_in[2];
    const float* bih0 = (const float*)d_in[3];
    const float* bhh0 = (const float*)d_in[4];
    const float* Wih1 = (const float*)d_in[5];
    const float* Whh1 = (const float*)d_in[6];
    const float* bih1 = (const float*)d_in[7];
    const float* bhh1 = (const float*)d_in[8];
    const float* Wfc  = (const float*)d_in[9];
    const float* bfc  = (const float*)d_in[10];
    float* out = (float*)d_out;

    __half *pWB0,*pWB1,*ph0,*ph1;
    float *pb0,*pb1,*pc0,*pc1,*pfcp;
    cudaGetSymbolAddress((void**)&pWB0, g_WB0);
    cudaGetSymbolAddress((void**)&pWB1, g_WB1);
    cudaGetSymbolAddress((void**)&pb0 , g_b0 );
    cudaGetSymbolAddress((void**)&pb1 , g_b1 );
    cudaGetSymbolAddress((void**)&ph0 , g_h0 );
    cudaGetSymbolAddress((void**)&ph1 , g_h1 );
    cudaGetSymbolAddress((void**)&pc0 , g_c0 );
    cudaGetSymbolAddress((void**)&pc1 , g_c1 );
    cudaGetSymbolAddress((void**)&pfcp, g_fcp);

    cudaFuncSetAttribute(lstm_cell, cudaFuncAttributeMaxDynamicSharedMemorySize, SMEM_TOTAL);

    prep_kernel<<<2048, 256>>>(Wih0, Whh0, bih0, bhh0, Wih1, Whh1, bih1, bhh1);

    dim3 grid(BATCH/128, 2);
    for (int t = 0; t < TSTEPS; t++) {
        int rp = t & 1, wp = 1 - rp;
        int use_bg = (t > LOOKBACK) ? 1 : 0;
        lstm_cell<<<grid, NTHR, SMEM_TOTAL>>>(
            inputs + t*DIN, TSTEPS*DIN,
            ph0 + rp*STATE, ph0 + rp*STATE,
            pWB0, KROW0, pb0,
            pc0, ph0 + wp*STATE,
            Wfc, bfc, pfcp, out,
            1, use_bg, t - 1 - LOOKBACK, 0);
        lstm_cell<<<grid, NTHR, SMEM_TOTAL>>>(
            nullptr, 0,
            ph0 + wp*STATE, ph1 + rp*STATE,
            pWB1, KROW1, pb1,
            pc1, ph1 + wp*STATE,
            Wfc, bfc, pfcp, out,
            0, 0, 0, (t >= LOOKBACK) ? 1 : 0);
    }
    fc_tail<<<BATCH/128, 128>>>(pfcp, bfc, out);
}